// round 15
// baseline (speedup 1.0000x reference)
#include <cuda_runtime.h>
#include <cuda_bf16.h>
#include <math.h>
#include <stdint.h>

#define BB 16
#define DD 128
#define LC 2048
#define LQ 512
#define NEGF (-1e30f)

// ---- scratch ----
__device__ float g_S[(size_t)BB * LC * LQ];
__device__ float g_V2[(size_t)BB * LQ * DD];
__device__ float g_V2p[(size_t)4 * BB * LQ * DD];
__device__ float g_sub0[BB * LC];
__device__ float g_sub1[BB * LQ];
__device__ float g_rmax[BB * LC], g_rinv[BB * LC];
__device__ float g_cmax[BB * LQ], g_cinv[BB * LQ];
__device__ float g_rpm[4 * BB * LC], g_rps[4 * BB * LC];
__device__ float g_cpm[16 * BB * LQ], g_cps[16 * BB * LQ];

// smem: 4 packed-bf16x2 tiles uint32[16][TSTR2] + AUX floats[1536]
#define TSTR2 136
#define TILE_U (16 * TSTR2)
#define SMEM_BYTES ((4 * TILE_U + 1536) * 4)

__device__ __forceinline__ void split2(float v0, float v1, uint32_t& H, uint32_t& L) {
    asm("cvt.rn.satfinite.bf16x2.f32 %0, %1, %2;" : "=r"(H) : "f"(v1), "f"(v0));
    float h0, h1;
    asm("{ .reg .b16 lo, hi;\n\t"
        "  mov.b32 {lo, hi}, %2;\n\t"
        "  cvt.f32.bf16 %0, lo;\n\t"
        "  cvt.f32.bf16 %1, hi; }"
        : "=f"(h0), "=f"(h1) : "r"(H));
    asm("cvt.rn.satfinite.bf16x2.f32 %0, %1, %2;" : "=r"(L) : "f"(v1 - h1), "f"(v0 - h0));
}

__device__ __forceinline__ void msum_merge(float& m, float& s, float m2, float s2) {
    float mn = fmaxf(m, m2);
    s = s * __expf(m - mn) + s2 * __expf(m2 - mn);
    m = mn;
}

#define MMA16(c, a, b0, b1)                                                   \
    asm volatile(                                                             \
        "mma.sync.aligned.m16n8k16.row.col.f32.bf16.bf16.f32 "                \
        "{%0,%1,%2,%3}, {%4,%5,%6,%7}, {%8,%9}, {%0,%1,%2,%3};"               \
        : "+f"((c)[0]), "+f"((c)[1]), "+f"((c)[2]), "+f"((c)[3])              \
        : "r"((a)[0]), "r"((a)[1]), "r"((a)[2]), "r"((a)[3]),                 \
          "r"(b0), "r"(b1))

// one BK=32 chunk; warp tile 32(m) x 64(n); tiles are [kpair][row] uint32
__device__ __forceinline__ void mma_chunk(const uint32_t* AH, const uint32_t* AL,
                                          const uint32_t* BH, const uint32_t* BL,
                                          float acc[2][8][4],
                                          int mbase, int nbase, int lane) {
    int lq = lane >> 2, kq = lane & 3;
    #pragma unroll
    for (int s = 0; s < 2; s++) {
        int kb = s * 8;
        uint32_t ah[2][4], al[2][4];
        #pragma unroll
        for (int ma = 0; ma < 2; ma++) {
            int r = mbase + 16 * ma + lq;
            ah[ma][0] = AH[(kb + kq) * TSTR2 + r];
            ah[ma][1] = AH[(kb + kq) * TSTR2 + r + 8];
            ah[ma][2] = AH[(kb + kq + 4) * TSTR2 + r];
            ah[ma][3] = AH[(kb + kq + 4) * TSTR2 + r + 8];
            al[ma][0] = AL[(kb + kq) * TSTR2 + r];
            al[ma][1] = AL[(kb + kq) * TSTR2 + r + 8];
            al[ma][2] = AL[(kb + kq + 4) * TSTR2 + r];
            al[ma][3] = AL[(kb + kq + 4) * TSTR2 + r + 8];
        }
        #pragma unroll
        for (int na = 0; na < 8; na++) {
            int c0 = nbase + 8 * na + lq;
            uint32_t bh0 = BH[(kb + kq) * TSTR2 + c0];
            uint32_t bh1 = BH[(kb + kq + 4) * TSTR2 + c0];
            uint32_t bl0 = BL[(kb + kq) * TSTR2 + c0];
            uint32_t bl1 = BL[(kb + kq + 4) * TSTR2 + c0];
            #pragma unroll
            for (int ma = 0; ma < 2; ma++) {
                MMA16(acc[ma][na], ah[ma], bh0, bh1);
                MMA16(acc[ma][na], ah[ma], bl0, bl1);
                MMA16(acc[ma][na], al[ma], bh0, bh1);
            }
        }
    }
}

// stage one column-half of a 128x128 fragment set into SP[row*68+col], then
// write coalesced float4 rows to dst (row stride = rstride)
__device__ __forceinline__ void store_half_coalesced(
    float* SP, float acc[2][8][4], float* dst, size_t rstride,
    int h, int wid, int lane, int mbase, int tid) {
    int lq = lane >> 2, kq = lane & 3;
    __syncthreads();
    if ((wid & 1) == h) {
        #pragma unroll
        for (int ma = 0; ma < 2; ma++)
            #pragma unroll
            for (int na = 0; na < 8; na++) {
                int r = mbase + 16 * ma + lq;
                int cl = 8 * na + kq * 2;
                SP[r * 68 + cl]           = acc[ma][na][0];
                SP[r * 68 + cl + 1]       = acc[ma][na][1];
                SP[(r + 8) * 68 + cl]     = acc[ma][na][2];
                SP[(r + 8) * 68 + cl + 1] = acc[ma][na][3];
            }
    }
    __syncthreads();
    #pragma unroll
    for (int it = 0; it < 8; it++) {
        int idx = tid + it * 256;
        int row = idx >> 4, c4 = (idx & 15) * 4;
        *(float4*)(dst + (size_t)row * rstride + h * 64 + c4) =
            *(const float4*)(SP + row * 68 + c4);
    }
}

// ============================================================
// K0: sub0 / sub1
// ============================================================
__global__ void k_sub(const float* __restrict__ C, const float* __restrict__ Q,
                      const float* __restrict__ w4C, const float* __restrict__ w4Q,
                      const float* __restrict__ bias) {
    int t = blockIdx.x * blockDim.x + threadIdx.x;
    const int totC = BB * LC;
    if (t < totC) {
        int b = t / LC, c = t % LC;
        const float* Cp = C + (size_t)b * DD * LC + c;
        float s = 0.f;
        #pragma unroll 8
        for (int d = 0; d < DD; d++) s += Cp[(size_t)d * LC] * w4C[d];
        g_sub0[t] = s;
    } else if (t < totC + BB * LQ) {
        int u = t - totC;
        int b = u / LQ, q = u % LQ;
        const float* Qp = Q + (size_t)b * DD * LQ + q;
        float s = bias[0];
        #pragma unroll 8
        for (int d = 0; d < DD; d++) s += Qp[(size_t)d * LQ] * w4Q[d];
        g_sub1[u] = s;
    }
}

// ============================================================
// K1: S = (C*w)^T Q + sub0 + sub1, stats fused, S-store staged+coalesced
// ============================================================
__global__ __launch_bounds__(256, 2) void k_scores(const float* __restrict__ C,
                                                   const float* __restrict__ Q,
                                                   const float* __restrict__ w4mlu,
                                                   const int* __restrict__ Qmask,
                                                   const int* __restrict__ Cmask) {
    extern __shared__ uint32_t smu[];
    uint32_t* TAH = smu;
    uint32_t* TAL = TAH + TILE_U;
    uint32_t* TBH = TAL + TILE_U;
    uint32_t* TBL = TBH + TILE_U;
    float* AUX = (float*)(TBL + TILE_U);
    int tid = threadIdx.x, wid = tid >> 5, lane = tid & 31;
    int b = blockIdx.z, cb = blockIdx.y * 128, qb = blockIdx.x * 128;
    int mbase = (wid >> 1) * 32, nbase = (wid & 1) * 64;
    const float* Cb = C + (size_t)b * DD * LC + cb;
    const float* Qb = Q + (size_t)b * DD * LQ + qb;

    if (tid < 128) {
        AUX[tid] = g_sub0[b * LC + cb + tid];
        AUX[128 + tid] = g_sub1[b * LQ + qb + tid];
        AUX[256 + tid] = Qmask[b * LQ + qb + tid] ? 0.f : NEGF;
        AUX[384 + tid] = Cmask[b * LC + cb + tid] ? 0.f : NEGF;
    }

    float acc[2][8][4];
    #pragma unroll
    for (int i = 0; i < 2; i++)
        #pragma unroll
        for (int j = 0; j < 8; j++)
            #pragma unroll
            for (int r = 0; r < 4; r++) acc[i][j][r] = 0.f;

    for (int k0 = 0; k0 < DD; k0 += 32) {
        #pragma unroll
        for (int it = 0; it < 4; it++) {
            int idx = tid + it * 256;
            int kp = idx >> 6;
            int cp = idx & 63;
            int c2 = cp * 2;
            int d0 = k0 + 2 * kp;
            float w0 = w4mlu[d0], w1 = w4mlu[d0 + 1];
            float2 a0 = *(const float2*)(Cb + (size_t)d0 * LC + c2);
            float2 a1 = *(const float2*)(Cb + (size_t)(d0 + 1) * LC + c2);
            uint32_t H0, L0, H1, L1;
            split2(a0.x * w0, a1.x * w1, H0, L0);
            split2(a0.y * w0, a1.y * w1, H1, L1);
            *(uint2*)&TAH[kp * TSTR2 + c2] = make_uint2(H0, H1);
            *(uint2*)&TAL[kp * TSTR2 + c2] = make_uint2(L0, L1);
            float2 q0 = *(const float2*)(Qb + (size_t)d0 * LQ + c2);
            float2 q1 = *(const float2*)(Qb + (size_t)(d0 + 1) * LQ + c2);
            split2(q0.x, q1.x, H0, L0);
            split2(q0.y, q1.y, H1, L1);
            *(uint2*)&TBH[kp * TSTR2 + c2] = make_uint2(H0, H1);
            *(uint2*)&TBL[kp * TSTR2 + c2] = make_uint2(L0, L1);
        }
        __syncthreads();
        mma_chunk(TAH, TAL, TBH, TBL, acc, mbase, nbase, lane);
        __syncthreads();
    }

    int lq = lane >> 2, kq = lane & 3;

    // finalize S in registers
    #pragma unroll
    for (int ma = 0; ma < 2; ma++)
        #pragma unroll
        for (int na = 0; na < 8; na++) {
            int r = mbase + 16 * ma + lq;
            int col = nbase + 8 * na + kq * 2;
            float s1a = AUX[128 + col], s1b = AUX[128 + col + 1];
            float s0a = AUX[r], s0b = AUX[r + 8];
            acc[ma][na][0] += s0a + s1a;
            acc[ma][na][1] += s0a + s1b;
            acc[ma][na][2] += s0b + s1a;
            acc[ma][na][3] += s0b + s1b;
        }

    // staged, coalesced S store
    float* SP = (float*)smu;
    float* Sdst = g_S + ((size_t)b * LC + cb) * LQ + qb;
    store_half_coalesced(SP, acc, Sdst, LQ, 0, wid, lane, mbase, tid);
    store_half_coalesced(SP, acc, Sdst, LQ, 1, wid, lane, mbase, tid);
    __syncthreads();

    // ---- row-stat partials ----
    float* SR = (float*)smu;
    float* SC = SR + 512;
    #pragma unroll
    for (int ma = 0; ma < 2; ma++)
        #pragma unroll
        for (int j = 0; j < 2; j++) {
            float m = -INFINITY;
            #pragma unroll
            for (int na = 0; na < 8; na++) {
                int col = nbase + 8 * na + kq * 2;
                m = fmaxf(m, fmaxf(acc[ma][na][2 * j] + AUX[256 + col],
                                   acc[ma][na][2 * j + 1] + AUX[256 + col + 1]));
            }
            float s = 0.f;
            #pragma unroll
            for (int na = 0; na < 8; na++) {
                int col = nbase + 8 * na + kq * 2;
                s += __expf(acc[ma][na][2 * j] + AUX[256 + col] - m) +
                     __expf(acc[ma][na][2 * j + 1] + AUX[256 + col + 1] - m);
            }
            #pragma unroll
            for (int o = 1; o <= 2; o <<= 1) {
                float m2 = __shfl_xor_sync(~0u, m, o);
                float s2 = __shfl_xor_sync(~0u, s, o);
                msum_merge(m, s, m2, s2);
            }
            if (kq == 0) {
                int row = mbase + 16 * ma + 8 * j + lq;
                SR[row * 4 + (wid & 1) * 2 + 0] = m;
                SR[row * 4 + (wid & 1) * 2 + 1] = s;
            }
        }

    // ---- col-stat partials ----
    #pragma unroll
    for (int na = 0; na < 8; na++)
        #pragma unroll
        for (int jj = 0; jj < 2; jj++) {
            float m = -INFINITY;
            #pragma unroll
            for (int ma = 0; ma < 2; ma++)
                #pragma unroll
                for (int j = 0; j < 2; j++) {
                    int row = mbase + 16 * ma + 8 * j + lq;
                    m = fmaxf(m, acc[ma][na][2 * j + jj] + AUX[384 + row]);
                }
            float s = 0.f;
            #pragma unroll
            for (int ma = 0; ma < 2; ma++)
                #pragma unroll
                for (int j = 0; j < 2; j++) {
                    int row = mbase + 16 * ma + 8 * j + lq;
                    s += __expf(acc[ma][na][2 * j + jj] + AUX[384 + row] - m);
                }
            #pragma unroll
            for (int o = 4; o <= 16; o <<= 1) {
                float m2 = __shfl_xor_sync(~0u, m, o);
                float s2 = __shfl_xor_sync(~0u, s, o);
                msum_merge(m, s, m2, s2);
            }
            if (lq == 0) {
                int col = nbase + 8 * na + kq * 2 + jj;
                SC[col * 8 + (wid >> 1) * 2 + 0] = m;
                SC[col * 8 + (wid >> 1) * 2 + 1] = s;
            }
        }
    __syncthreads();

    if (tid < 128) {
        float M = SR[tid * 4], S = SR[tid * 4 + 1];
        msum_merge(M, S, SR[tid * 4 + 2], SR[tid * 4 + 3]);
        size_t ri = ((size_t)blockIdx.x * BB + b) * LC + cb + tid;
        g_rpm[ri] = M; g_rps[ri] = S;
        float Mc = SC[tid * 8], Sc = SC[tid * 8 + 1];
        #pragma unroll
        for (int g = 1; g < 4; g++) msum_merge(Mc, Sc, SC[tid * 8 + 2 * g], SC[tid * 8 + 2 * g + 1]);
        size_t ci = ((size_t)blockIdx.y * BB + b) * LQ + qb + tid;
        g_cpm[ci] = Mc; g_cps[ci] = Sc;
    }
}

// ============================================================
// stat merges
// ============================================================
__global__ void k_rmerge() {
    int t = blockIdx.x * 256 + threadIdx.x;
    if (t >= BB * LC) return;
    float M = g_rpm[t], S = g_rps[t];
    #pragma unroll
    for (int g = 1; g < 4; g++) msum_merge(M, S, g_rpm[(size_t)g * BB * LC + t], g_rps[(size_t)g * BB * LC + t]);
    g_rmax[t] = M; g_rinv[t] = 1.f / S;
}

__global__ void k_cmerge() {
    int t = blockIdx.x * 256 + threadIdx.x;
    if (t >= BB * LQ) return;
    float M = g_cpm[t], S = g_cps[t];
    #pragma unroll
    for (int g = 1; g < 16; g++) msum_merge(M, S, g_cpm[(size_t)g * BB * LQ + t], g_cps[(size_t)g * BB * LQ + t]);
    g_cmax[t] = M; g_cinv[t] = 1.f / S;
}

// ============================================================
// K4: V2 partials [m=q, n=d, k=c], split-K=4; staged coalesced epilogue
// ============================================================
__global__ __launch_bounds__(256, 2) void k_gemmV2(const float* __restrict__ C,
                                                   const int* __restrict__ Cmask) {
    extern __shared__ uint32_t smu[];
    uint32_t* TAH = smu;
    uint32_t* TAL = TAH + TILE_U;
    uint32_t* TBH = TAL + TILE_U;
    uint32_t* TBL = TBH + TILE_U;
    float* AUX = (float*)(TBL + TILE_U);
    int tid = threadIdx.x, wid = tid >> 5, lane = tid & 31;
    int b = blockIdx.z, part = blockIdx.y, qb = blockIdx.x * 128;
    int mbase = (wid >> 1) * 32, nbase = (wid & 1) * 64;
    int c0chunk = part * 512;

    if (tid < 128) {
        AUX[tid] = g_cmax[b * LQ + qb + tid];
        AUX[128 + tid] = g_cinv[b * LQ + qb + tid];
    }
    for (int i = tid; i < 512; i += 256) AUX[256 + i] = Cmask[b * LC + c0chunk + i] ? 0.f : NEGF;
    __syncthreads();

    float acc[2][8][4];
    #pragma unroll
    for (int i = 0; i < 2; i++)
        #pragma unroll
        for (int j = 0; j < 8; j++)
            #pragma unroll
            for (int r = 0; r < 4; r++) acc[i][j][r] = 0.f;

    const float* Cb = C + (size_t)b * DD * LC;
    const float* Sb = g_S + ((size_t)b * LC + c0chunk) * LQ + qb;

    for (int k0 = 0; k0 < 512; k0 += 32) {
        #pragma unroll
        for (int it = 0; it < 4; it++) {
            int idx = tid + it * 256;
            int kp = idx >> 6;
            int qp = idx & 63;
            int q2 = qp * 2;
            int cg = k0 + 2 * kp;
            float2 v0 = *(const float2*)(Sb + (size_t)cg * LQ + q2);
            float2 v1 = *(const float2*)(Sb + (size_t)(cg + 1) * LQ + q2);
            float ca0 = AUX[256 + cg], ca1 = AUX[256 + cg + 1];
            float e00 = __expf(v0.x + ca0 - AUX[q2]) * AUX[128 + q2];
            float e10 = __expf(v1.x + ca1 - AUX[q2]) * AUX[128 + q2];
            float e01 = __expf(v0.y + ca0 - AUX[q2 + 1]) * AUX[128 + q2 + 1];
            float e11 = __expf(v1.y + ca1 - AUX[q2 + 1]) * AUX[128 + q2 + 1];
            uint32_t H0, L0, H1, L1;
            split2(e00, e10, H0, L0);
            split2(e01, e11, H1, L1);
            *(uint2*)&TAH[kp * TSTR2 + q2] = make_uint2(H0, H1);
            *(uint2*)&TAL[kp * TSTR2 + q2] = make_uint2(L0, L1);
        }
        #pragma unroll
        for (int p = 0; p < 4; p++) {
            int row = (tid >> 3) + p * 32;
            int cc = (tid & 7) * 4;
            int kp = (tid & 7) * 2;
            float4 w = *(const float4*)(Cb + (size_t)row * LC + c0chunk + k0 + cc);
            uint32_t H, L;
            split2(w.x, w.y, H, L);
            TBH[kp * TSTR2 + row] = H; TBL[kp * TSTR2 + row] = L;
            split2(w.z, w.w, H, L);
            TBH[(kp + 1) * TSTR2 + row] = H; TBL[(kp + 1) * TSTR2 + row] = L;
        }
        __syncthreads();
        mma_chunk(TAH, TAL, TBH, TBL, acc, mbase, nbase, lane);
        __syncthreads();
    }

    float* SP = (float*)smu;
    float* Vp = g_V2p + ((size_t)part * BB * LQ + (size_t)b * LQ + qb) * DD;
    store_half_coalesced(SP, acc, Vp, DD, 0, wid, lane, mbase, tid);
    store_half_coalesced(SP, acc, Vp, DD, 1, wid, lane, mbase, tid);
}

__global__ void k_reduceV2() {
    const int n = BB * LQ * DD / 4;
    int i = blockIdx.x * blockDim.x + threadIdx.x;
    if (i < n) {
        const float4* p = (const float4*)g_V2p;
        float4 a = p[i], b2 = p[i + n], c = p[i + 2 * n], d = p[i + 3 * n];
        float4 o;
        o.x = a.x + b2.x + c.x + d.x;
        o.y = a.y + b2.y + c.y + d.y;
        o.z = a.z + b2.z + c.z + d.z;
        o.w = a.w + b2.w + c.w + d.w;
        ((float4*)g_V2)[i] = o;
    }
}

// ============================================================
// K5: FUSED  A = S1 @ Qt, Bmat = S1 @ V2, + assemble epilogue
// ============================================================
__global__ __launch_bounds__(256, 1) void k_gemmAB(const float* __restrict__ Q,
                                                   const int* __restrict__ Qmask,
                                                   const float* __restrict__ C,
                                                   float* __restrict__ out) {
    extern __shared__ uint32_t smu[];
    uint32_t* TAH = smu;
    uint32_t* TAL = TAH + TILE_U;
    uint32_t* TBH = TAL + TILE_U;
    uint32_t* TBL = TBH + TILE_U;
    float* AUX = (float*)(TBL + TILE_U);
    int tid = threadIdx.x, wid = tid >> 5, lane = tid & 31;
    int b = blockIdx.y, cb = blockIdx.x * 128;
    int mbase = (wid >> 1) * 32, nbase = (wid & 1) * 64;

    if (tid < 128) {
        AUX[tid] = g_rmax[b * LC + cb + tid];
        AUX[128 + tid] = g_rinv[b * LC + cb + tid];
    }
    for (int i = tid; i < 512; i += 256) AUX[256 + i] = Qmask[b * LQ + i] ? 0.f : NEGF;
    __syncthreads();

    float accA[2][8][4], accB[2][8][4];
    #pragma unroll
    for (int i = 0; i < 2; i++)
        #pragma unroll
        for (int j = 0; j < 8; j++)
            #pragma unroll
            for (int r = 0; r < 4; r++) { accA[i][j][r] = 0.f; accB[i][j][r] = 0.f; }

    const float* Sb = g_S + ((size_t)b * LC + cb) * LQ;
    const float* Qb = Q + (size_t)b * DD * LQ;
    const float* Vb = g_V2 + (size_t)b * LQ * DD;

    for (int k0 = 0; k0 < LQ; k0 += 32) {
        #pragma unroll
        for (int p = 0; p < 4; p++) {
            int row = (tid >> 3) + p * 32;
            int qq = (tid & 7) * 4;
            int kp = (tid & 7) * 2;
            float4 v = *(const float4*)(Sb + (size_t)row * LQ + k0 + qq);
            float rm = AUX[row], ri = AUX[128 + row];
            float e0 = __expf(v.x + AUX[256 + k0 + qq + 0] - rm) * ri;
            float e1 = __expf(v.y + AUX[256 + k0 + qq + 1] - rm) * ri;
            float e2 = __expf(v.z + AUX[256 + k0 + qq + 2] - rm) * ri;
            float e3 = __expf(v.w + AUX[256 + k0 + qq + 3] - rm) * ri;
            uint32_t H, L;
            split2(e0, e1, H, L);
            TAH[kp * TSTR2 + row] = H; TAL[kp * TSTR2 + row] = L;
            split2(e2, e3, H, L);
            TAH[(kp + 1) * TSTR2 + row] = H; TAL[(kp + 1) * TSTR2 + row] = L;
            float4 w = *(const float4*)(Qb + (size_t)row * LQ + k0 + qq);
            split2(w.x, w.y, H, L);
            TBH[kp * TSTR2 + row] = H; TBL[kp * TSTR2 + row] = L;
            split2(w.z, w.w, H, L);
            TBH[(kp + 1) * TSTR2 + row] = H; TBL[(kp + 1) * TSTR2 + row] = L;
        }
        __syncthreads();
        mma_chunk(TAH, TAL, TBH, TBL, accA, mbase, nbase, lane);
        __syncthreads();
        #pragma unroll
        for (int it = 0; it < 2; it++) {
            int idx = tid + it * 256;
            int kp = idx >> 5;
            int dp = idx & 31;
            int d2 = dp * 4;
            int qg = k0 + 2 * kp;
            float4 v0 = *(const float4*)(Vb + (size_t)qg * DD + d2);
            float4 v1 = *(const float4*)(Vb + (size_t)(qg + 1) * DD + d2);
            uint32_t H0, L0, H1, L1;
            split2(v0.x, v1.x, H0, L0);
            split2(v0.y, v1.y, H1, L1);
            *(uint2*)&TBH[kp * TSTR2 + d2] = make_uint2(H0, H1);
            *(uint2*)&TBL[kp * TSTR2 + d2] = make_uint2(L0, L1);
            split2(v0.z, v1.z, H0, L0);
            split2(v0.w, v1.w, H1, L1);
            *(uint2*)&TBH[kp * TSTR2 + d2 + 2] = make_uint2(H0, H1);
            *(uint2*)&TBL[kp * TSTR2 + d2 + 2] = make_uint2(L0, L1);
        }
        __syncthreads();
        mma_chunk(TAH, TAL, TBH, TBL, accB, mbase, nbase, lane);
        __syncthreads();
    }

    // ---- fused assemble epilogue ----
    float* SP = (float*)smu;
    const float* Cb2 = C + (size_t)b * DD * LC + cb;
    float* outB = out + (size_t)b * 4 * DD * LC + cb;
    int lq = lane >> 2, kq = lane & 3;

    #pragma unroll
    for (int sel = 0; sel < 2; sel++) {
        #pragma unroll
        for (int h = 0; h < 2; h++) {
            __syncthreads();
            if ((wid & 1) == h) {
                #pragma unroll
                for (int ma = 0; ma < 2; ma++)
                    #pragma unroll
                    for (int na = 0; na < 8; na++) {
                        int r = mbase + 16 * ma + lq;
                        int cl = 8 * na + kq * 2;
                        float v0, v1, v2, v3;
                        if (sel == 0) {
                            v0 = accA[ma][na][0]; v1 = accA[ma][na][1];
                            v2 = accA[ma][na][2]; v3 = accA[ma][na][3];
                        } else {
                            v0 = accB[ma][na][0]; v1 = accB[ma][na][1];
                            v2 = accB[ma][na][2]; v3 = accB[ma][na][3];
                        }
                        SP[cl * 132 + r]           = v0;
                        SP[(cl + 1) * 132 + r]     = v1;
                        SP[cl * 132 + r + 8]       = v2;
                        SP[(cl + 1) * 132 + r + 8] = v3;
                    }
            }
            __syncthreads();
            #pragma unroll
            for (int it = 0; it < 8; it++) {
                int idx = tid + it * 256;
                int dl = idx >> 5, c4 = (idx & 31) * 4;
                int d = 64 * h + dl;
                float4 cv = *(const float4*)(Cb2 + (size_t)d * LC + c4);
                float4 av = *(const float4*)(SP + dl * 132 + c4);
                float4 pr = make_float4(cv.x * av.x, cv.y * av.y, cv.z * av.z, cv.w * av.w);
                if (sel == 0) {
                    *(float4*)(outB + (size_t)d * LC + c4) = cv;
                    *(float4*)(outB + (size_t)(DD + d) * LC + c4) = av;
                    *(float4*)(outB + (size_t)(2 * DD + d) * LC + c4) = pr;
                } else {
                    *(float4*)(outB + (size_t)(3 * DD + d) * LC + c4) = pr;
                }
            }
        }
    }
}

extern "C" void kernel_launch(void* const* d_in, const int* in_sizes, int n_in,
                              void* d_out, int out_size) {
    const float* C = (const float*)d_in[0];
    const float* Q = (const float*)d_in[1];
    const int* Cmask = (const int*)d_in[2];
    const int* Qmask = (const int*)d_in[3];
    const float* w4C = (const float*)d_in[4];
    const float* w4Q = (const float*)d_in[5];
    const float* w4mlu = (const float*)d_in[6];
    const float* bias = (const float*)d_in[7];
    float* out = (float*)d_out;

    cudaFuncSetAttribute(k_scores, cudaFuncAttributeMaxDynamicSharedMemorySize, SMEM_BYTES);
    cudaFuncSetAttribute(k_gemmV2, cudaFuncAttributeMaxDynamicSharedMemorySize, SMEM_BYTES);
    cudaFuncSetAttribute(k_gemmAB, cudaFuncAttributeMaxDynamicSharedMemorySize, SMEM_BYTES);

    int nsub = BB * LC + BB * LQ;
    k_sub<<<(nsub + 255) / 256, 256>>>(C, Q, w4C, w4Q, bias);
    k_scores<<<dim3(4, 16, 16), 256, SMEM_BYTES>>>(C, Q, w4mlu, Qmask, Cmask);
    k_rmerge<<<(BB * LC + 255) / 256, 256>>>();
    k_cmerge<<<(BB * LQ + 255) / 256, 256>>>();
    k_gemmV2<<<dim3(4, 4, 16), 256, SMEM_BYTES>>>(C, Cmask);
    k_reduceV2<<<(BB * LQ * DD / 4 + 255) / 256, 256>>>();
    k_gemmAB<<<dim3(16, 16), 256, SMEM_BYTES>>>(Q, Qmask, C, out);
}

// round 16
// speedup vs baseline: 1.0299x; 1.0299x over previous
#include <cuda_runtime.h>
#include <cuda_bf16.h>
#include <math.h>
#include <stdint.h>

#define BB 16
#define DD 128
#define LC 2048
#define LQ 512
#define NEGF (-1e30f)

// ---- scratch ----
__device__ float g_S[(size_t)BB * LC * LQ];
__device__ float g_V2[(size_t)BB * LQ * DD];
__device__ float g_V2p[(size_t)4 * BB * LQ * DD];
__device__ float g_sub0[BB * LC];
__device__ float g_sub1[BB * LQ];
__device__ float g_rmax[BB * LC], g_rinv[BB * LC];
__device__ float g_cmax[BB * LQ], g_cinv[BB * LQ];
__device__ float g_rpm[4 * BB * LC], g_rps[4 * BB * LC];
__device__ float g_cpm[16 * BB * LQ], g_cps[16 * BB * LQ];

// smem: 4 packed-bf16x2 tiles uint32[16][TSTR2] + AUX floats[1536]
#define TSTR2 136
#define TILE_U (16 * TSTR2)
#define SMEM_BYTES ((4 * TILE_U + 1536) * 4)

__device__ __forceinline__ void split2(float v0, float v1, uint32_t& H, uint32_t& L) {
    asm("cvt.rn.satfinite.bf16x2.f32 %0, %1, %2;" : "=r"(H) : "f"(v1), "f"(v0));
    float h0, h1;
    asm("{ .reg .b16 lo, hi;\n\t"
        "  mov.b32 {lo, hi}, %2;\n\t"
        "  cvt.f32.bf16 %0, lo;\n\t"
        "  cvt.f32.bf16 %1, hi; }"
        : "=f"(h0), "=f"(h1) : "r"(H));
    asm("cvt.rn.satfinite.bf16x2.f32 %0, %1, %2;" : "=r"(L) : "f"(v1 - h1), "f"(v0 - h0));
}

__device__ __forceinline__ void msum_merge(float& m, float& s, float m2, float s2) {
    float mn = fmaxf(m, m2);
    s = s * __expf(m - mn) + s2 * __expf(m2 - mn);
    m = mn;
}

#define MMA16(c, a, b0, b1)                                                   \
    asm volatile(                                                             \
        "mma.sync.aligned.m16n8k16.row.col.f32.bf16.bf16.f32 "                \
        "{%0,%1,%2,%3}, {%4,%5,%6,%7}, {%8,%9}, {%0,%1,%2,%3};"               \
        : "+f"((c)[0]), "+f"((c)[1]), "+f"((c)[2]), "+f"((c)[3])              \
        : "r"((a)[0]), "r"((a)[1]), "r"((a)[2]), "r"((a)[3]),                 \
          "r"(b0), "r"(b1))

// one BK=32 chunk; warp tile 32(m) x 64(n); tiles are [kpair][row] uint32
__device__ __forceinline__ void mma_chunk(const uint32_t* AH, const uint32_t* AL,
                                          const uint32_t* BH, const uint32_t* BL,
                                          float acc[2][8][4],
                                          int mbase, int nbase, int lane) {
    int lq = lane >> 2, kq = lane & 3;
    #pragma unroll
    for (int s = 0; s < 2; s++) {
        int kb = s * 8;
        uint32_t ah[2][4], al[2][4];
        #pragma unroll
        for (int ma = 0; ma < 2; ma++) {
            int r = mbase + 16 * ma + lq;
            ah[ma][0] = AH[(kb + kq) * TSTR2 + r];
            ah[ma][1] = AH[(kb + kq) * TSTR2 + r + 8];
            ah[ma][2] = AH[(kb + kq + 4) * TSTR2 + r];
            ah[ma][3] = AH[(kb + kq + 4) * TSTR2 + r + 8];
            al[ma][0] = AL[(kb + kq) * TSTR2 + r];
            al[ma][1] = AL[(kb + kq) * TSTR2 + r + 8];
            al[ma][2] = AL[(kb + kq + 4) * TSTR2 + r];
            al[ma][3] = AL[(kb + kq + 4) * TSTR2 + r + 8];
        }
        #pragma unroll
        for (int na = 0; na < 8; na++) {
            int c0 = nbase + 8 * na + lq;
            uint32_t bh0 = BH[(kb + kq) * TSTR2 + c0];
            uint32_t bh1 = BH[(kb + kq + 4) * TSTR2 + c0];
            uint32_t bl0 = BL[(kb + kq) * TSTR2 + c0];
            uint32_t bl1 = BL[(kb + kq + 4) * TSTR2 + c0];
            #pragma unroll
            for (int ma = 0; ma < 2; ma++) {
                MMA16(acc[ma][na], ah[ma], bh0, bh1);
                MMA16(acc[ma][na], ah[ma], bl0, bl1);
                MMA16(acc[ma][na], al[ma], bh0, bh1);
            }
        }
    }
}

// ============================================================
// K0: sub0 / sub1
// ============================================================
__global__ void k_sub(const float* __restrict__ C, const float* __restrict__ Q,
                      const float* __restrict__ w4C, const float* __restrict__ w4Q,
                      const float* __restrict__ bias) {
    int t = blockIdx.x * blockDim.x + threadIdx.x;
    const int totC = BB * LC;
    if (t < totC) {
        int b = t / LC, c = t % LC;
        const float* Cp = C + (size_t)b * DD * LC + c;
        float s = 0.f;
        #pragma unroll 8
        for (int d = 0; d < DD; d++) s += Cp[(size_t)d * LC] * w4C[d];
        g_sub0[t] = s;
    } else if (t < totC + BB * LQ) {
        int u = t - totC;
        int b = u / LQ, q = u % LQ;
        const float* Qp = Q + (size_t)b * DD * LQ + q;
        float s = bias[0];
        #pragma unroll 8
        for (int d = 0; d < DD; d++) s += Qp[(size_t)d * LQ] * w4Q[d];
        g_sub1[u] = s;
    }
}

// ============================================================
// K1: S = (C*w)^T Q + sub0 + sub1, plus per-block softmax stat partials
// fills COALESCED: column index fastest across warp
// ============================================================
__global__ __launch_bounds__(256, 2) void k_scores(const float* __restrict__ C,
                                                   const float* __restrict__ Q,
                                                   const float* __restrict__ w4mlu,
                                                   const int* __restrict__ Qmask,
                                                   const int* __restrict__ Cmask) {
    extern __shared__ uint32_t smu[];
    uint32_t* TAH = smu;
    uint32_t* TAL = TAH + TILE_U;
    uint32_t* TBH = TAL + TILE_U;
    uint32_t* TBL = TBH + TILE_U;
    float* AUX = (float*)(TBL + TILE_U);
    int tid = threadIdx.x, wid = tid >> 5, lane = tid & 31;
    int b = blockIdx.z, cb = blockIdx.y * 128, qb = blockIdx.x * 128;
    int mbase = (wid >> 1) * 32, nbase = (wid & 1) * 64;
    const float* Cb = C + (size_t)b * DD * LC + cb;
    const float* Qb = Q + (size_t)b * DD * LQ + qb;

    if (tid < 128) {
        AUX[tid] = g_sub0[b * LC + cb + tid];
        AUX[128 + tid] = g_sub1[b * LQ + qb + tid];
        AUX[256 + tid] = Qmask[b * LQ + qb + tid] ? 0.f : NEGF;
        AUX[384 + tid] = Cmask[b * LC + cb + tid] ? 0.f : NEGF;
    }

    float acc[2][8][4];
    #pragma unroll
    for (int i = 0; i < 2; i++)
        #pragma unroll
        for (int j = 0; j < 8; j++)
            #pragma unroll
            for (int r = 0; r < 4; r++) acc[i][j][r] = 0.f;

    for (int k0 = 0; k0 < DD; k0 += 32) {
        #pragma unroll
        for (int it = 0; it < 4; it++) {
            int idx = tid + it * 256;
            int kp = idx >> 6;          // 0..15, constant across 64 threads
            int cp = idx & 63;          // column-pair fastest -> coalesced
            int c2 = cp * 2;
            int d0 = k0 + 2 * kp;
            float w0 = w4mlu[d0], w1 = w4mlu[d0 + 1];
            float2 a0 = *(const float2*)(Cb + (size_t)d0 * LC + c2);
            float2 a1 = *(const float2*)(Cb + (size_t)(d0 + 1) * LC + c2);
            uint32_t H0, L0, H1, L1;
            split2(a0.x * w0, a1.x * w1, H0, L0);
            split2(a0.y * w0, a1.y * w1, H1, L1);
            *(uint2*)&TAH[kp * TSTR2 + c2] = make_uint2(H0, H1);
            *(uint2*)&TAL[kp * TSTR2 + c2] = make_uint2(L0, L1);
            float2 q0 = *(const float2*)(Qb + (size_t)d0 * LQ + c2);
            float2 q1 = *(const float2*)(Qb + (size_t)(d0 + 1) * LQ + c2);
            split2(q0.x, q1.x, H0, L0);
            split2(q0.y, q1.y, H1, L1);
            *(uint2*)&TBH[kp * TSTR2 + c2] = make_uint2(H0, H1);
            *(uint2*)&TBL[kp * TSTR2 + c2] = make_uint2(L0, L1);
        }
        __syncthreads();
        mma_chunk(TAH, TAL, TBH, TBL, acc, mbase, nbase, lane);
        __syncthreads();
    }

    int lq = lane >> 2, kq = lane & 3;

    #pragma unroll
    for (int ma = 0; ma < 2; ma++)
        #pragma unroll
        for (int na = 0; na < 8; na++) {
            int r = mbase + 16 * ma + lq;
            int col = nbase + 8 * na + kq * 2;
            float s1a = AUX[128 + col], s1b = AUX[128 + col + 1];
            float s0a = AUX[r], s0b = AUX[r + 8];
            acc[ma][na][0] += s0a + s1a;
            acc[ma][na][1] += s0a + s1b;
            acc[ma][na][2] += s0b + s1a;
            acc[ma][na][3] += s0b + s1b;
            float* o0 = g_S + ((size_t)b * LC + cb + r) * LQ + qb + col;
            float* o1 = g_S + ((size_t)b * LC + cb + r + 8) * LQ + qb + col;
            *(float2*)o0 = make_float2(acc[ma][na][0], acc[ma][na][1]);
            *(float2*)o1 = make_float2(acc[ma][na][2], acc[ma][na][3]);
        }

    // ---- row-stat partials ----
    float* SR = (float*)smu;
    float* SC = SR + 512;
    #pragma unroll
    for (int ma = 0; ma < 2; ma++)
        #pragma unroll
        for (int j = 0; j < 2; j++) {
            float m = -INFINITY;
            #pragma unroll
            for (int na = 0; na < 8; na++) {
                int col = nbase + 8 * na + kq * 2;
                m = fmaxf(m, fmaxf(acc[ma][na][2 * j] + AUX[256 + col],
                                   acc[ma][na][2 * j + 1] + AUX[256 + col + 1]));
            }
            float s = 0.f;
            #pragma unroll
            for (int na = 0; na < 8; na++) {
                int col = nbase + 8 * na + kq * 2;
                s += __expf(acc[ma][na][2 * j] + AUX[256 + col] - m) +
                     __expf(acc[ma][na][2 * j + 1] + AUX[256 + col + 1] - m);
            }
            #pragma unroll
            for (int o = 1; o <= 2; o <<= 1) {
                float m2 = __shfl_xor_sync(~0u, m, o);
                float s2 = __shfl_xor_sync(~0u, s, o);
                msum_merge(m, s, m2, s2);
            }
            if (kq == 0) {
                int row = mbase + 16 * ma + 8 * j + lq;
                SR[row * 4 + (wid & 1) * 2 + 0] = m;
                SR[row * 4 + (wid & 1) * 2 + 1] = s;
            }
        }

    // ---- col-stat partials ----
    #pragma unroll
    for (int na = 0; na < 8; na++)
        #pragma unroll
        for (int jj = 0; jj < 2; jj++) {
            float m = -INFINITY;
            #pragma unroll
            for (int ma = 0; ma < 2; ma++)
                #pragma unroll
                for (int j = 0; j < 2; j++) {
                    int row = mbase + 16 * ma + 8 * j + lq;
                    m = fmaxf(m, acc[ma][na][2 * j + jj] + AUX[384 + row]);
                }
            float s = 0.f;
            #pragma unroll
            for (int ma = 0; ma < 2; ma++)
                #pragma unroll
                for (int j = 0; j < 2; j++) {
                    int row = mbase + 16 * ma + 8 * j + lq;
                    s += __expf(acc[ma][na][2 * j + jj] + AUX[384 + row] - m);
                }
            #pragma unroll
            for (int o = 4; o <= 16; o <<= 1) {
                float m2 = __shfl_xor_sync(~0u, m, o);
                float s2 = __shfl_xor_sync(~0u, s, o);
                msum_merge(m, s, m2, s2);
            }
            if (lq == 0) {
                int col = nbase + 8 * na + kq * 2 + jj;
                SC[col * 8 + (wid >> 1) * 2 + 0] = m;
                SC[col * 8 + (wid >> 1) * 2 + 1] = s;
            }
        }
    __syncthreads();

    if (tid < 128) {
        float M = SR[tid * 4], S = SR[tid * 4 + 1];
        msum_merge(M, S, SR[tid * 4 + 2], SR[tid * 4 + 3]);
        size_t ri = ((size_t)blockIdx.x * BB + b) * LC + cb + tid;
        g_rpm[ri] = M; g_rps[ri] = S;
        float Mc = SC[tid * 8], Sc = SC[tid * 8 + 1];
        #pragma unroll
        for (int g = 1; g < 4; g++) msum_merge(Mc, Sc, SC[tid * 8 + 2 * g], SC[tid * 8 + 2 * g + 1]);
        size_t ci = ((size_t)blockIdx.y * BB + b) * LQ + qb + tid;
        g_cpm[ci] = Mc; g_cps[ci] = Sc;
    }
}

// ============================================================
// stat merges
// ============================================================
__global__ void k_rmerge() {
    int t = blockIdx.x * 256 + threadIdx.x;
    if (t >= BB * LC) return;
    float M = g_rpm[t], S = g_rps[t];
    #pragma unroll
    for (int g = 1; g < 4; g++) msum_merge(M, S, g_rpm[(size_t)g * BB * LC + t], g_rps[(size_t)g * BB * LC + t]);
    g_rmax[t] = M; g_rinv[t] = 1.f / S;
}

__global__ void k_cmerge() {
    int t = blockIdx.x * 256 + threadIdx.x;
    if (t >= BB * LQ) return;
    float M = g_cpm[t], S = g_cps[t];
    #pragma unroll
    for (int g = 1; g < 16; g++) msum_merge(M, S, g_cpm[(size_t)g * BB * LQ + t], g_cps[(size_t)g * BB * LQ + t]);
    g_cmax[t] = M; g_cinv[t] = 1.f / S;
}

// ============================================================
// K4: V2 partials [m=q, n=d, k=c], split-K=4; A-fill coalesced (q fastest)
// ============================================================
__global__ __launch_bounds__(256, 2) void k_gemmV2(const float* __restrict__ C,
                                                   const int* __restrict__ Cmask) {
    extern __shared__ uint32_t smu[];
    uint32_t* TAH = smu;
    uint32_t* TAL = TAH + TILE_U;
    uint32_t* TBH = TAL + TILE_U;
    uint32_t* TBL = TBH + TILE_U;
    float* AUX = (float*)(TBL + TILE_U);
    int tid = threadIdx.x, wid = tid >> 5, lane = tid & 31;
    int b = blockIdx.z, part = blockIdx.y, qb = blockIdx.x * 128;
    int mbase = (wid >> 1) * 32, nbase = (wid & 1) * 64;
    int c0chunk = part * 512;

    if (tid < 128) {
        AUX[tid] = g_cmax[b * LQ + qb + tid];
        AUX[128 + tid] = g_cinv[b * LQ + qb + tid];
    }
    for (int i = tid; i < 512; i += 256) AUX[256 + i] = Cmask[b * LC + c0chunk + i] ? 0.f : NEGF;
    __syncthreads();

    float acc[2][8][4];
    #pragma unroll
    for (int i = 0; i < 2; i++)
        #pragma unroll
        for (int j = 0; j < 8; j++)
            #pragma unroll
            for (int r = 0; r < 4; r++) acc[i][j][r] = 0.f;

    const float* Cb = C + (size_t)b * DD * LC;
    const float* Sb = g_S + ((size_t)b * LC + c0chunk) * LQ + qb;

    for (int k0 = 0; k0 < 512; k0 += 32) {
        #pragma unroll
        for (int it = 0; it < 4; it++) {
            int idx = tid + it * 256;
            int kp = idx >> 6;        // c-pair, constant across 64 threads
            int qp = idx & 63;        // q fastest -> coalesced
            int q2 = qp * 2;
            int cg = k0 + 2 * kp;
            float2 v0 = *(const float2*)(Sb + (size_t)cg * LQ + q2);
            float2 v1 = *(const float2*)(Sb + (size_t)(cg + 1) * LQ + q2);
            float ca0 = AUX[256 + cg], ca1 = AUX[256 + cg + 1];
            float e00 = __expf(v0.x + ca0 - AUX[q2]) * AUX[128 + q2];
            float e10 = __expf(v1.x + ca1 - AUX[q2]) * AUX[128 + q2];
            float e01 = __expf(v0.y + ca0 - AUX[q2 + 1]) * AUX[128 + q2 + 1];
            float e11 = __expf(v1.y + ca1 - AUX[q2 + 1]) * AUX[128 + q2 + 1];
            uint32_t H0, L0, H1, L1;
            split2(e00, e10, H0, L0);
            split2(e01, e11, H1, L1);
            *(uint2*)&TAH[kp * TSTR2 + q2] = make_uint2(H0, H1);
            *(uint2*)&TAL[kp * TSTR2 + q2] = make_uint2(L0, L1);
        }
        #pragma unroll
        for (int p = 0; p < 4; p++) {
            int row = (tid >> 3) + p * 32;
            int cc = (tid & 7) * 4;
            int kp = (tid & 7) * 2;
            float4 w = *(const float4*)(Cb + (size_t)row * LC + c0chunk + k0 + cc);
            uint32_t H, L;
            split2(w.x, w.y, H, L);
            TBH[kp * TSTR2 + row] = H; TBL[kp * TSTR2 + row] = L;
            split2(w.z, w.w, H, L);
            TBH[(kp + 1) * TSTR2 + row] = H; TBL[(kp + 1) * TSTR2 + row] = L;
        }
        __syncthreads();
        mma_chunk(TAH, TAL, TBH, TBL, acc, mbase, nbase, lane);
        __syncthreads();
    }

    int lq = lane >> 2, kq = lane & 3;
    float* Vp = g_V2p + ((size_t)part * BB * LQ + (size_t)b * LQ + qb) * DD;
    #pragma unroll
    for (int ma = 0; ma < 2; ma++)
        #pragma unroll
        for (int na = 0; na < 8; na++) {
            int r = mbase + 16 * ma + lq;
            int col = nbase + 8 * na + kq * 2;
            *(float2*)(Vp + (size_t)r * DD + col) =
                make_float2(acc[ma][na][0], acc[ma][na][1]);
            *(float2*)(Vp + (size_t)(r + 8) * DD + col) =
                make_float2(acc[ma][na][2], acc[ma][na][3]);
        }
}

__global__ void k_reduceV2() {
    const int n = BB * LQ * DD / 4;
    int i = blockIdx.x * blockDim.x + threadIdx.x;
    if (i < n) {
        const float4* p = (const float4*)g_V2p;
        float4 a = p[i], b2 = p[i + n], c = p[i + 2 * n], d = p[i + 3 * n];
        float4 o;
        o.x = a.x + b2.x + c.x + d.x;
        o.y = a.y + b2.y + c.y + d.y;
        o.z = a.z + b2.z + c.z + d.z;
        o.w = a.w + b2.w + c.w + d.w;
        ((float4*)g_V2)[i] = o;
    }
}

// ============================================================
// K5: FUSED  A = S1 @ Qt, Bmat = S1 @ V2, + assemble epilogue
// V2-fill coalesced (d fastest)
// ============================================================
__global__ __launch_bounds__(256, 1) void k_gemmAB(const float* __restrict__ Q,
                                                   const int* __restrict__ Qmask,
                                                   const float* __restrict__ C,
                                                   float* __restrict__ out) {
    extern __shared__ uint32_t smu[];
    uint32_t* TAH = smu;
    uint32_t* TAL = TAH + TILE_U;
    uint32_t* TBH = TAL + TILE_U;
    uint32_t* TBL = TBH + TILE_U;
    float* AUX = (float*)(TBL + TILE_U);
    int tid = threadIdx.x, wid = tid >> 5, lane = tid & 31;
    int b = blockIdx.y, cb = blockIdx.x * 128;
    int mbase = (wid >> 1) * 32, nbase = (wid & 1) * 64;

    if (tid < 128) {
        AUX[tid] = g_rmax[b * LC + cb + tid];
        AUX[128 + tid] = g_rinv[b * LC + cb + tid];
    }
    for (int i = tid; i < 512; i += 256) AUX[256 + i] = Qmask[b * LQ + i] ? 0.f : NEGF;
    __syncthreads();

    float accA[2][8][4], accB[2][8][4];
    #pragma unroll
    for (int i = 0; i < 2; i++)
        #pragma unroll
        for (int j = 0; j < 8; j++)
            #pragma unroll
            for (int r = 0; r < 4; r++) { accA[i][j][r] = 0.f; accB[i][j][r] = 0.f; }

    const float* Sb = g_S + ((size_t)b * LC + cb) * LQ;
    const float* Qb = Q + (size_t)b * DD * LQ;
    const float* Vb = g_V2 + (size_t)b * LQ * DD;

    for (int k0 = 0; k0 < LQ; k0 += 32) {
        #pragma unroll
        for (int p = 0; p < 4; p++) {
            int row = (tid >> 3) + p * 32;
            int qq = (tid & 7) * 4;
            int kp = (tid & 7) * 2;
            float4 v = *(const float4*)(Sb + (size_t)row * LQ + k0 + qq);
            float rm = AUX[row], ri = AUX[128 + row];
            float e0 = __expf(v.x + AUX[256 + k0 + qq + 0] - rm) * ri;
            float e1 = __expf(v.y + AUX[256 + k0 + qq + 1] - rm) * ri;
            float e2 = __expf(v.z + AUX[256 + k0 + qq + 2] - rm) * ri;
            float e3 = __expf(v.w + AUX[256 + k0 + qq + 3] - rm) * ri;
            uint32_t H, L;
            split2(e0, e1, H, L);
            TAH[kp * TSTR2 + row] = H; TAL[kp * TSTR2 + row] = L;
            split2(e2, e3, H, L);
            TAH[(kp + 1) * TSTR2 + row] = H; TAL[(kp + 1) * TSTR2 + row] = L;
            float4 w = *(const float4*)(Qb + (size_t)row * LQ + k0 + qq);
            split2(w.x, w.y, H, L);
            TBH[kp * TSTR2 + row] = H; TBL[kp * TSTR2 + row] = L;
            split2(w.z, w.w, H, L);
            TBH[(kp + 1) * TSTR2 + row] = H; TBL[(kp + 1) * TSTR2 + row] = L;
        }
        __syncthreads();
        mma_chunk(TAH, TAL, TBH, TBL, accA, mbase, nbase, lane);
        __syncthreads();
        #pragma unroll
        for (int it = 0; it < 2; it++) {
            int idx = tid + it * 256;
            int kp = idx >> 5;        // q-pair, constant across 32 threads
            int dp = idx & 31;        // d fastest -> coalesced float4
            int d2 = dp * 4;
            int qg = k0 + 2 * kp;
            float4 v0 = *(const float4*)(Vb + (size_t)qg * DD + d2);
            float4 v1 = *(const float4*)(Vb + (size_t)(qg + 1) * DD + d2);
            uint32_t H0, L0, H1, L1;
            split2(v0.x, v1.x, H0, L0);
            split2(v0.y, v1.y, H1, L1);
            *(uint2*)&TBH[kp * TSTR2 + d2] = make_uint2(H0, H1);
            *(uint2*)&TBL[kp * TSTR2 + d2] = make_uint2(L0, L1);
            split2(v0.z, v1.z, H0, L0);
            split2(v0.w, v1.w, H1, L1);
            *(uint2*)&TBH[kp * TSTR2 + d2 + 2] = make_uint2(H0, H1);
            *(uint2*)&TBL[kp * TSTR2 + d2 + 2] = make_uint2(L0, L1);
        }
        __syncthreads();
        mma_chunk(TAH, TAL, TBH, TBL, accB, mbase, nbase, lane);
        __syncthreads();
    }

    // ---- fused assemble epilogue ----
    float* SP = (float*)smu;
    const float* Cb2 = C + (size_t)b * DD * LC + cb;
    float* outB = out + (size_t)b * 4 * DD * LC + cb;
    int lq = lane >> 2, kq = lane & 3;

    #pragma unroll
    for (int sel = 0; sel < 2; sel++) {
        #pragma unroll
        for (int h = 0; h < 2; h++) {
            __syncthreads();
            if ((wid & 1) == h) {
                #pragma unroll
                for (int ma = 0; ma < 2; ma++)
                    #pragma unroll
                    for (int na = 0; na < 8; na++) {
                        int r = mbase + 16 * ma + lq;
                        int cl = 8 * na + kq * 2;
                        float v0, v1, v2, v3;
                        if (sel == 0) {
                            v0 = accA[ma][na][0]; v1 = accA[ma][na][1];
                            v2 = accA[ma][na][2]; v3 = accA[ma][na][3];
                        } else {
                            v0 = accB[ma][na][0]; v1 = accB[ma][na][1];
                            v2 = accB[ma][na][2]; v3 = accB[ma][na][3];
                        }
                        SP[cl * 132 + r]           = v0;
                        SP[(cl + 1) * 132 + r]     = v1;
                        SP[cl * 132 + r + 8]       = v2;
                        SP[(cl + 1) * 132 + r + 8] = v3;
                    }
            }
            __syncthreads();
            #pragma unroll
            for (int it = 0; it < 8; it++) {
                int idx = tid + it * 256;
                int dl = idx >> 5, c4 = (idx & 31) * 4;
                int d = 64 * h + dl;
                float4 cv = *(const float4*)(Cb2 + (size_t)d * LC + c4);
                float4 av = *(const float4*)(SP + dl * 132 + c4);
                float4 pr = make_float4(cv.x * av.x, cv.y * av.y, cv.z * av.z, cv.w * av.w);
                if (sel == 0) {
                    *(float4*)(outB + (size_t)d * LC + c4) = cv;
                    *(float4*)(outB + (size_t)(DD + d) * LC + c4) = av;
                    *(float4*)(outB + (size_t)(2 * DD + d) * LC + c4) = pr;
                } else {
                    *(float4*)(outB + (size_t)(3 * DD + d) * LC + c4) = pr;
                }
            }
        }
    }
}

extern "C" void kernel_launch(void* const* d_in, const int* in_sizes, int n_in,
                              void* d_out, int out_size) {
    const float* C = (const float*)d_in[0];
    const float* Q = (const float*)d_in[1];
    const int* Cmask = (const int*)d_in[2];
    const int* Qmask = (const int*)d_in[3];
    const float* w4C = (const float*)d_in[4];
    const float* w4Q = (const float*)d_in[5];
    const float* w4mlu = (const float*)d_in[6];
    const float* bias = (const float*)d_in[7];
    float* out = (float*)d_out;

    cudaFuncSetAttribute(k_scores, cudaFuncAttributeMaxDynamicSharedMemorySize, SMEM_BYTES);
    cudaFuncSetAttribute(k_gemmV2, cudaFuncAttributeMaxDynamicSharedMemorySize, SMEM_BYTES);
    cudaFuncSetAttribute(k_gemmAB, cudaFuncAttributeMaxDynamicSharedMemorySize, SMEM_BYTES);

    int nsub = BB * LC + BB * LQ;
    k_sub<<<(nsub + 255) / 256, 256>>>(C, Q, w4C, w4Q, bias);
    k_scores<<<dim3(4, 16, 16), 256, SMEM_BYTES>>>(C, Q, w4mlu, Qmask, Cmask);
    k_rmerge<<<(BB * LC + 255) / 256, 256>>>();
    k_cmerge<<<(BB * LQ + 255) / 256, 256>>>();
    k_gemmV2<<<dim3(4, 4, 16), 256, SMEM_BYTES>>>(C, Cmask);
    k_reduceV2<<<(BB * LQ * DD / 4 + 255) / 256, 256>>>();
    k_gemmAB<<<dim3(16, 16), 256, SMEM_BYTES>>>(Q, Qmask, C, out);
}

// round 17
// speedup vs baseline: 1.1736x; 1.1396x over previous
#include <cuda_runtime.h>
#include <cuda_bf16.h>
#include <math.h>
#include <stdint.h>

#define BB 16
#define DD 128
#define LC 2048
#define LQ 512
#define NEGF (-1e30f)

// ---- scratch ----
__device__ float g_S[(size_t)BB * LC * LQ];
__device__ float g_V2[(size_t)BB * LQ * DD];
__device__ float g_V2p[(size_t)4 * BB * LQ * DD];
__device__ float g_sub0[BB * LC];
__device__ float g_sub1[BB * LQ];
__device__ float g_rmax[BB * LC], g_rinv[BB * LC];
__device__ float g_cmax[BB * LQ], g_cinv[BB * LQ];
__device__ float g_rpm[4 * BB * LC], g_rps[4 * BB * LC];
__device__ float g_cpm[16 * BB * LQ], g_cps[16 * BB * LQ];

// smem: 4 packed-bf16x2 tiles uint32[16][TSTR2] + AUX floats[1536]
#define TSTR2 136
#define TILE_U (16 * TSTR2)
#define SMEM_BYTES ((4 * TILE_U + 1536) * 4)

__device__ __forceinline__ void split2(float v0, float v1, uint32_t& H, uint32_t& L) {
    asm("cvt.rn.satfinite.bf16x2.f32 %0, %1, %2;" : "=r"(H) : "f"(v1), "f"(v0));
    float h0, h1;
    asm("{ .reg .b16 lo, hi;\n\t"
        "  mov.b32 {lo, hi}, %2;\n\t"
        "  cvt.f32.bf16 %0, lo;\n\t"
        "  cvt.f32.bf16 %1, hi; }"
        : "=f"(h0), "=f"(h1) : "r"(H));
    asm("cvt.rn.satfinite.bf16x2.f32 %0, %1, %2;" : "=r"(L) : "f"(v1 - h1), "f"(v0 - h0));
}

__device__ __forceinline__ void msum_merge(float& m, float& s, float m2, float s2) {
    float mn = fmaxf(m, m2);
    s = s * __expf(m - mn) + s2 * __expf(m2 - mn);
    m = mn;
}

#define MMA16(c, a, b0, b1)                                                   \
    asm volatile(                                                             \
        "mma.sync.aligned.m16n8k16.row.col.f32.bf16.bf16.f32 "                \
        "{%0,%1,%2,%3}, {%4,%5,%6,%7}, {%8,%9}, {%0,%1,%2,%3};"               \
        : "+f"((c)[0]), "+f"((c)[1]), "+f"((c)[2]), "+f"((c)[3])              \
        : "r"((a)[0]), "r"((a)[1]), "r"((a)[2]), "r"((a)[3]),                 \
          "r"(b0), "r"(b1))

// one BK=32 chunk; warp tile 32(m) x 64(n); tiles are [kpair][row] uint32
__device__ __forceinline__ void mma_chunk(const uint32_t* AH, const uint32_t* AL,
                                          const uint32_t* BH, const uint32_t* BL,
                                          float acc[2][8][4],
                                          int mbase, int nbase, int lane) {
    int lq = lane >> 2, kq = lane & 3;
    #pragma unroll
    for (int s = 0; s < 2; s++) {
        int kb = s * 8;
        uint32_t ah[2][4], al[2][4];
        #pragma unroll
        for (int ma = 0; ma < 2; ma++) {
            int r = mbase + 16 * ma + lq;
            ah[ma][0] = AH[(kb + kq) * TSTR2 + r];
            ah[ma][1] = AH[(kb + kq) * TSTR2 + r + 8];
            ah[ma][2] = AH[(kb + kq + 4) * TSTR2 + r];
            ah[ma][3] = AH[(kb + kq + 4) * TSTR2 + r + 8];
            al[ma][0] = AL[(kb + kq) * TSTR2 + r];
            al[ma][1] = AL[(kb + kq) * TSTR2 + r + 8];
            al[ma][2] = AL[(kb + kq + 4) * TSTR2 + r];
            al[ma][3] = AL[(kb + kq + 4) * TSTR2 + r + 8];
        }
        #pragma unroll
        for (int na = 0; na < 8; na++) {
            int c0 = nbase + 8 * na + lq;
            uint32_t bh0 = BH[(kb + kq) * TSTR2 + c0];
            uint32_t bh1 = BH[(kb + kq + 4) * TSTR2 + c0];
            uint32_t bl0 = BL[(kb + kq) * TSTR2 + c0];
            uint32_t bl1 = BL[(kb + kq + 4) * TSTR2 + c0];
            #pragma unroll
            for (int ma = 0; ma < 2; ma++) {
                MMA16(acc[ma][na], ah[ma], bh0, bh1);
                MMA16(acc[ma][na], ah[ma], bl0, bl1);
                MMA16(acc[ma][na], al[ma], bh0, bh1);
            }
        }
    }
}

// ============================================================
// K0: sub0 / sub1
// ============================================================
__global__ void k_sub(const float* __restrict__ C, const float* __restrict__ Q,
                      const float* __restrict__ w4C, const float* __restrict__ w4Q,
                      const float* __restrict__ bias) {
    int t = blockIdx.x * blockDim.x + threadIdx.x;
    const int totC = BB * LC;
    if (t < totC) {
        int b = t / LC, c = t % LC;
        const float* Cp = C + (size_t)b * DD * LC + c;
        float s = 0.f;
        #pragma unroll 8
        for (int d = 0; d < DD; d++) s += Cp[(size_t)d * LC] * w4C[d];
        g_sub0[t] = s;
    } else if (t < totC + BB * LQ) {
        int u = t - totC;
        int b = u / LQ, q = u % LQ;
        const float* Qp = Q + (size_t)b * DD * LQ + q;
        float s = bias[0];
        #pragma unroll 8
        for (int d = 0; d < DD; d++) s += Qp[(size_t)d * LQ] * w4Q[d];
        g_sub1[u] = s;
    }
}

// ============================================================
// K1: S = (C*w)^T Q + sub0 + sub1, plus per-block softmax stat partials
// ============================================================
__global__ __launch_bounds__(256, 2) void k_scores(const float* __restrict__ C,
                                                   const float* __restrict__ Q,
                                                   const float* __restrict__ w4mlu,
                                                   const int* __restrict__ Qmask,
                                                   const int* __restrict__ Cmask) {
    extern __shared__ uint32_t smu[];
    uint32_t* TAH = smu;
    uint32_t* TAL = TAH + TILE_U;
    uint32_t* TBH = TAL + TILE_U;
    uint32_t* TBL = TBH + TILE_U;
    float* AUX = (float*)(TBL + TILE_U);
    int tid = threadIdx.x, wid = tid >> 5, lane = tid & 31;
    int b = blockIdx.z, cb = blockIdx.y * 128, qb = blockIdx.x * 128;
    int mbase = (wid >> 1) * 32, nbase = (wid & 1) * 64;
    const float* Cb = C + (size_t)b * DD * LC + cb;
    const float* Qb = Q + (size_t)b * DD * LQ + qb;

    if (tid < 128) {
        AUX[tid] = g_sub0[b * LC + cb + tid];
        AUX[128 + tid] = g_sub1[b * LQ + qb + tid];
        AUX[256 + tid] = Qmask[b * LQ + qb + tid] ? 0.f : NEGF;
        AUX[384 + tid] = Cmask[b * LC + cb + tid] ? 0.f : NEGF;
    }

    float acc[2][8][4];
    #pragma unroll
    for (int i = 0; i < 2; i++)
        #pragma unroll
        for (int j = 0; j < 8; j++)
            #pragma unroll
            for (int r = 0; r < 4; r++) acc[i][j][r] = 0.f;

    for (int k0 = 0; k0 < DD; k0 += 32) {
        #pragma unroll
        for (int it = 0; it < 4; it++) {
            int idx = tid + it * 256;
            int kp = idx >> 6;
            int cp = idx & 63;
            int c2 = cp * 2;
            int d0 = k0 + 2 * kp;
            float w0 = w4mlu[d0], w1 = w4mlu[d0 + 1];
            float2 a0 = *(const float2*)(Cb + (size_t)d0 * LC + c2);
            float2 a1 = *(const float2*)(Cb + (size_t)(d0 + 1) * LC + c2);
            uint32_t H0, L0, H1, L1;
            split2(a0.x * w0, a1.x * w1, H0, L0);
            split2(a0.y * w0, a1.y * w1, H1, L1);
            *(uint2*)&TAH[kp * TSTR2 + c2] = make_uint2(H0, H1);
            *(uint2*)&TAL[kp * TSTR2 + c2] = make_uint2(L0, L1);
            float2 q0 = *(const float2*)(Qb + (size_t)d0 * LQ + c2);
            float2 q1 = *(const float2*)(Qb + (size_t)(d0 + 1) * LQ + c2);
            split2(q0.x, q1.x, H0, L0);
            split2(q0.y, q1.y, H1, L1);
            *(uint2*)&TBH[kp * TSTR2 + c2] = make_uint2(H0, H1);
            *(uint2*)&TBL[kp * TSTR2 + c2] = make_uint2(L0, L1);
        }
        __syncthreads();
        mma_chunk(TAH, TAL, TBH, TBL, acc, mbase, nbase, lane);
        __syncthreads();
    }

    int lq = lane >> 2, kq = lane & 3;

    #pragma unroll
    for (int ma = 0; ma < 2; ma++)
        #pragma unroll
        for (int na = 0; na < 8; na++) {
            int r = mbase + 16 * ma + lq;
            int col = nbase + 8 * na + kq * 2;
            float s1a = AUX[128 + col], s1b = AUX[128 + col + 1];
            float s0a = AUX[r], s0b = AUX[r + 8];
            acc[ma][na][0] += s0a + s1a;
            acc[ma][na][1] += s0a + s1b;
            acc[ma][na][2] += s0b + s1a;
            acc[ma][na][3] += s0b + s1b;
            float* o0 = g_S + ((size_t)b * LC + cb + r) * LQ + qb + col;
            float* o1 = g_S + ((size_t)b * LC + cb + r + 8) * LQ + qb + col;
            *(float2*)o0 = make_float2(acc[ma][na][0], acc[ma][na][1]);
            *(float2*)o1 = make_float2(acc[ma][na][2], acc[ma][na][3]);
        }

    // ---- row-stat partials ----
    float* SR = (float*)smu;
    float* SC = SR + 512;
    #pragma unroll
    for (int ma = 0; ma < 2; ma++)
        #pragma unroll
        for (int j = 0; j < 2; j++) {
            float m = -INFINITY;
            #pragma unroll
            for (int na = 0; na < 8; na++) {
                int col = nbase + 8 * na + kq * 2;
                m = fmaxf(m, fmaxf(acc[ma][na][2 * j] + AUX[256 + col],
                                   acc[ma][na][2 * j + 1] + AUX[256 + col + 1]));
            }
            float s = 0.f;
            #pragma unroll
            for (int na = 0; na < 8; na++) {
                int col = nbase + 8 * na + kq * 2;
                s += __expf(acc[ma][na][2 * j] + AUX[256 + col] - m) +
                     __expf(acc[ma][na][2 * j + 1] + AUX[256 + col + 1] - m);
            }
            #pragma unroll
            for (int o = 1; o <= 2; o <<= 1) {
                float m2 = __shfl_xor_sync(~0u, m, o);
                float s2 = __shfl_xor_sync(~0u, s, o);
                msum_merge(m, s, m2, s2);
            }
            if (kq == 0) {
                int row = mbase + 16 * ma + 8 * j + lq;
                SR[row * 4 + (wid & 1) * 2 + 0] = m;
                SR[row * 4 + (wid & 1) * 2 + 1] = s;
            }
        }

    // ---- col-stat partials ----
    #pragma unroll
    for (int na = 0; na < 8; na++)
        #pragma unroll
        for (int jj = 0; jj < 2; jj++) {
            float m = -INFINITY;
            #pragma unroll
            for (int ma = 0; ma < 2; ma++)
                #pragma unroll
                for (int j = 0; j < 2; j++) {
                    int row = mbase + 16 * ma + 8 * j + lq;
                    m = fmaxf(m, acc[ma][na][2 * j + jj] + AUX[384 + row]);
                }
            float s = 0.f;
            #pragma unroll
            for (int ma = 0; ma < 2; ma++)
                #pragma unroll
                for (int j = 0; j < 2; j++) {
                    int row = mbase + 16 * ma + 8 * j + lq;
                    s += __expf(acc[ma][na][2 * j + jj] + AUX[384 + row] - m);
                }
            #pragma unroll
            for (int o = 4; o <= 16; o <<= 1) {
                float m2 = __shfl_xor_sync(~0u, m, o);
                float s2 = __shfl_xor_sync(~0u, s, o);
                msum_merge(m, s, m2, s2);
            }
            if (lq == 0) {
                int col = nbase + 8 * na + kq * 2 + jj;
                SC[col * 8 + (wid >> 1) * 2 + 0] = m;
                SC[col * 8 + (wid >> 1) * 2 + 1] = s;
            }
        }
    __syncthreads();

    if (tid < 128) {
        float M = SR[tid * 4], S = SR[tid * 4 + 1];
        msum_merge(M, S, SR[tid * 4 + 2], SR[tid * 4 + 3]);
        size_t ri = ((size_t)blockIdx.x * BB + b) * LC + cb + tid;
        g_rpm[ri] = M; g_rps[ri] = S;
        float Mc = SC[tid * 8], Sc = SC[tid * 8 + 1];
        #pragma unroll
        for (int g = 1; g < 4; g++) msum_merge(Mc, Sc, SC[tid * 8 + 2 * g], SC[tid * 8 + 2 * g + 1]);
        size_t ci = ((size_t)blockIdx.y * BB + b) * LQ + qb + tid;
        g_cpm[ci] = Mc; g_cps[ci] = Sc;
    }
}

// ============================================================
// stat merges
// ============================================================
__global__ void k_rmerge() {
    int t = blockIdx.x * 256 + threadIdx.x;
    if (t >= BB * LC) return;
    float M = g_rpm[t], S = g_rps[t];
    #pragma unroll
    for (int g = 1; g < 4; g++) msum_merge(M, S, g_rpm[(size_t)g * BB * LC + t], g_rps[(size_t)g * BB * LC + t]);
    g_rmax[t] = M; g_rinv[t] = 1.f / S;
}

__global__ void k_cmerge() {
    int t = blockIdx.x * 256 + threadIdx.x;
    if (t >= BB * LQ) return;
    float M = g_cpm[t], S = g_cps[t];
    #pragma unroll
    for (int g = 1; g < 16; g++) msum_merge(M, S, g_cpm[(size_t)g * BB * LQ + t], g_cps[(size_t)g * BB * LQ + t]);
    g_cmax[t] = M; g_cinv[t] = 1.f / S;
}

// ============================================================
// K4: V2 partials [m=q, n=d, k=c], split-K=4; A-fill coalesced (q fastest)
// ============================================================
__global__ __launch_bounds__(256, 2) void k_gemmV2(const float* __restrict__ C,
                                                   const int* __restrict__ Cmask) {
    extern __shared__ uint32_t smu[];
    uint32_t* TAH = smu;
    uint32_t* TAL = TAH + TILE_U;
    uint32_t* TBH = TAL + TILE_U;
    uint32_t* TBL = TBH + TILE_U;
    float* AUX = (float*)(TBL + TILE_U);
    int tid = threadIdx.x, wid = tid >> 5, lane = tid & 31;
    int b = blockIdx.z, part = blockIdx.y, qb = blockIdx.x * 128;
    int mbase = (wid >> 1) * 32, nbase = (wid & 1) * 64;
    int c0chunk = part * 512;

    if (tid < 128) {
        AUX[tid] = g_cmax[b * LQ + qb + tid];
        AUX[128 + tid] = g_cinv[b * LQ + qb + tid];
    }
    for (int i = tid; i < 512; i += 256) AUX[256 + i] = Cmask[b * LC + c0chunk + i] ? 0.f : NEGF;
    __syncthreads();

    float acc[2][8][4];
    #pragma unroll
    for (int i = 0; i < 2; i++)
        #pragma unroll
        for (int j = 0; j < 8; j++)
            #pragma unroll
            for (int r = 0; r < 4; r++) acc[i][j][r] = 0.f;

    const float* Cb = C + (size_t)b * DD * LC;
    const float* Sb = g_S + ((size_t)b * LC + c0chunk) * LQ + qb;

    for (int k0 = 0; k0 < 512; k0 += 32) {
        #pragma unroll
        for (int it = 0; it < 4; it++) {
            int idx = tid + it * 256;
            int kp = idx >> 6;
            int qp = idx & 63;
            int q2 = qp * 2;
            int cg = k0 + 2 * kp;
            float2 v0 = *(const float2*)(Sb + (size_t)cg * LQ + q2);
            float2 v1 = *(const float2*)(Sb + (size_t)(cg + 1) * LQ + q2);
            float ca0 = AUX[256 + cg], ca1 = AUX[256 + cg + 1];
            float e00 = __expf(v0.x + ca0 - AUX[q2]) * AUX[128 + q2];
            float e10 = __expf(v1.x + ca1 - AUX[q2]) * AUX[128 + q2];
            float e01 = __expf(v0.y + ca0 - AUX[q2 + 1]) * AUX[128 + q2 + 1];
            float e11 = __expf(v1.y + ca1 - AUX[q2 + 1]) * AUX[128 + q2 + 1];
            uint32_t H0, L0, H1, L1;
            split2(e00, e10, H0, L0);
            split2(e01, e11, H1, L1);
            *(uint2*)&TAH[kp * TSTR2 + q2] = make_uint2(H0, H1);
            *(uint2*)&TAL[kp * TSTR2 + q2] = make_uint2(L0, L1);
        }
        #pragma unroll
        for (int p = 0; p < 4; p++) {
            int row = (tid >> 3) + p * 32;
            int cc = (tid & 7) * 4;
            int kp = (tid & 7) * 2;
            float4 w = *(const float4*)(Cb + (size_t)row * LC + c0chunk + k0 + cc);
            uint32_t H, L;
            split2(w.x, w.y, H, L);
            TBH[kp * TSTR2 + row] = H; TBL[kp * TSTR2 + row] = L;
            split2(w.z, w.w, H, L);
            TBH[(kp + 1) * TSTR2 + row] = H; TBL[(kp + 1) * TSTR2 + row] = L;
        }
        __syncthreads();
        mma_chunk(TAH, TAL, TBH, TBL, acc, mbase, nbase, lane);
        __syncthreads();
    }

    int lq = lane >> 2, kq = lane & 3;
    float* Vp = g_V2p + ((size_t)part * BB * LQ + (size_t)b * LQ + qb) * DD;
    #pragma unroll
    for (int ma = 0; ma < 2; ma++)
        #pragma unroll
        for (int na = 0; na < 8; na++) {
            int r = mbase + 16 * ma + lq;
            int col = nbase + 8 * na + kq * 2;
            *(float2*)(Vp + (size_t)r * DD + col) =
                make_float2(acc[ma][na][0], acc[ma][na][1]);
            *(float2*)(Vp + (size_t)(r + 8) * DD + col) =
                make_float2(acc[ma][na][2], acc[ma][na][3]);
        }
}

__global__ void k_reduceV2() {
    const int n = BB * LQ * DD / 4;
    int i = blockIdx.x * blockDim.x + threadIdx.x;
    if (i < n) {
        const float4* p = (const float4*)g_V2p;
        float4 a = p[i], b2 = p[i + n], c = p[i + 2 * n], d = p[i + 3 * n];
        float4 o;
        o.x = a.x + b2.x + c.x + d.x;
        o.y = a.y + b2.y + c.y + d.y;
        o.z = a.z + b2.z + c.z + d.z;
        o.w = a.w + b2.w + c.w + d.w;
        ((float4*)g_V2)[i] = o;
    }
}

// ============================================================
// K5: FUSED  A = S1 @ Qt, Bmat = S1 @ V2, + assemble epilogue
// software-pipelined: gmem loads prefetched into regs, overlapped with MMA
// ============================================================
__global__ __launch_bounds__(256, 1) void k_gemmAB(const float* __restrict__ Q,
                                                   const int* __restrict__ Qmask,
                                                   const float* __restrict__ C,
                                                   float* __restrict__ out) {
    extern __shared__ uint32_t smu[];
    uint32_t* TAH = smu;
    uint32_t* TAL = TAH + TILE_U;
    uint32_t* TBH = TAL + TILE_U;
    uint32_t* TBL = TBH + TILE_U;
    float* AUX = (float*)(TBL + TILE_U);
    int tid = threadIdx.x, wid = tid >> 5, lane = tid & 31;
    int b = blockIdx.y, cb = blockIdx.x * 128;
    int mbase = (wid >> 1) * 32, nbase = (wid & 1) * 64;

    if (tid < 128) {
        AUX[tid] = g_rmax[b * LC + cb + tid];
        AUX[128 + tid] = g_rinv[b * LC + cb + tid];
    }
    for (int i = tid; i < 512; i += 256) AUX[256 + i] = Qmask[b * LQ + i] ? 0.f : NEGF;
    __syncthreads();

    float accA[2][8][4], accB[2][8][4];
    #pragma unroll
    for (int i = 0; i < 2; i++)
        #pragma unroll
        for (int j = 0; j < 8; j++)
            #pragma unroll
            for (int r = 0; r < 4; r++) { accA[i][j][r] = 0.f; accB[i][j][r] = 0.f; }

    const float* Sb = g_S + ((size_t)b * LC + cb) * LQ;
    const float* Qb = Q + (size_t)b * DD * LQ;
    const float* Vb = g_V2 + (size_t)b * LQ * DD;

    // prefetch chunk 0 S/Q
    float4 psv[4], pwv[4];
    #pragma unroll
    for (int p = 0; p < 4; p++) {
        int row = (tid >> 3) + p * 32;
        int qq = (tid & 7) * 4;
        psv[p] = *(const float4*)(Sb + (size_t)row * LQ + qq);
        pwv[p] = *(const float4*)(Qb + (size_t)row * LQ + qq);
    }

    for (int k0 = 0; k0 < LQ; k0 += 32) {
        // store A (exp S1) and B (Qt) from prefetched regs
        #pragma unroll
        for (int p = 0; p < 4; p++) {
            int row = (tid >> 3) + p * 32;
            int qq = (tid & 7) * 4;
            int kp = (tid & 7) * 2;
            float4 v = psv[p];
            float rm = AUX[row], ri = AUX[128 + row];
            float e0 = __expf(v.x + AUX[256 + k0 + qq + 0] - rm) * ri;
            float e1 = __expf(v.y + AUX[256 + k0 + qq + 1] - rm) * ri;
            float e2 = __expf(v.z + AUX[256 + k0 + qq + 2] - rm) * ri;
            float e3 = __expf(v.w + AUX[256 + k0 + qq + 3] - rm) * ri;
            uint32_t H, L;
            split2(e0, e1, H, L);
            TAH[kp * TSTR2 + row] = H; TAL[kp * TSTR2 + row] = L;
            split2(e2, e3, H, L);
            TAH[(kp + 1) * TSTR2 + row] = H; TAL[(kp + 1) * TSTR2 + row] = L;
            float4 w = pwv[p];
            split2(w.x, w.y, H, L);
            TBH[kp * TSTR2 + row] = H; TBL[kp * TSTR2 + row] = L;
            split2(w.z, w.w, H, L);
            TBH[(kp + 1) * TSTR2 + row] = H; TBL[(kp + 1) * TSTR2 + row] = L;
        }
        __syncthreads();
        // prefetch this chunk's V2 (overlaps with mma accA)
        float4 vv0[2], vv1[2];
        #pragma unroll
        for (int it = 0; it < 2; it++) {
            int idx = tid + it * 256;
            int kp2 = idx >> 5;
            int dp = idx & 31;
            int d2 = dp * 4;
            int qg = k0 + 2 * kp2;
            vv0[it] = *(const float4*)(Vb + (size_t)qg * DD + d2);
            vv1[it] = *(const float4*)(Vb + (size_t)(qg + 1) * DD + d2);
        }
        mma_chunk(TAH, TAL, TBH, TBL, accA, mbase, nbase, lane);
        __syncthreads();
        // store B tile with V2
        #pragma unroll
        for (int it = 0; it < 2; it++) {
            int idx = tid + it * 256;
            int kp2 = idx >> 5;
            int dp = idx & 31;
            int d2 = dp * 4;
            float4 v0 = vv0[it], v1 = vv1[it];
            uint32_t H0, L0, H1, L1;
            split2(v0.x, v1.x, H0, L0);
            split2(v0.y, v1.y, H1, L1);
            *(uint2*)&TBH[kp2 * TSTR2 + d2] = make_uint2(H0, H1);
            *(uint2*)&TBL[kp2 * TSTR2 + d2] = make_uint2(L0, L1);
            split2(v0.z, v1.z, H0, L0);
            split2(v0.w, v1.w, H1, L1);
            *(uint2*)&TBH[kp2 * TSTR2 + d2 + 2] = make_uint2(H0, H1);
            *(uint2*)&TBL[kp2 * TSTR2 + d2 + 2] = make_uint2(L0, L1);
        }
        __syncthreads();
        // prefetch next chunk's S/Q (overlaps with mma accB)
        if (k0 + 32 < LQ) {
            #pragma unroll
            for (int p = 0; p < 4; p++) {
                int row = (tid >> 3) + p * 32;
                int qq = (tid & 7) * 4;
                psv[p] = *(const float4*)(Sb + (size_t)row * LQ + k0 + 32 + qq);
                pwv[p] = *(const float4*)(Qb + (size_t)row * LQ + k0 + 32 + qq);
            }
        }
        mma_chunk(TAH, TAL, TBH, TBL, accB, mbase, nbase, lane);
        __syncthreads();
    }

    // ---- fused assemble epilogue ----
    float* SP = (float*)smu;
    const float* Cb2 = C + (size_t)b * DD * LC + cb;
    float* outB = out + (size_t)b * 4 * DD * LC + cb;
    int lq = lane >> 2, kq = lane & 3;

    #pragma unroll
    for (int sel = 0; sel < 2; sel++) {
        #pragma unroll
        for (int h = 0; h < 2; h++) {
            __syncthreads();
            if ((wid & 1) == h) {
                #pragma unroll
                for (int ma = 0; ma < 2; ma++)
                    #pragma unroll
                    for (int na = 0; na < 8; na++) {
                        int r = mbase + 16 * ma + lq;
                        int cl = 8 * na + kq * 2;
                        float v0, v1, v2, v3;
                        if (sel == 0) {
                            v0 = accA[ma][na][0]; v1 = accA[ma][na][1];
                            v2 = accA[ma][na][2]; v3 = accA[ma][na][3];
                        } else {
                            v0 = accB[ma][na][0]; v1 = accB[ma][na][1];
                            v2 = accB[ma][na][2]; v3 = accB[ma][na][3];
                        }
                        SP[cl * 132 + r]           = v0;
                        SP[(cl + 1) * 132 + r]     = v1;
                        SP[cl * 132 + r + 8]       = v2;
                        SP[(cl + 1) * 132 + r + 8] = v3;
                    }
            }
            __syncthreads();
            #pragma unroll
            for (int it = 0; it < 8; it++) {
                int idx = tid + it * 256;
                int dl = idx >> 5, c4 = (idx & 31) * 4;
                int d = 64 * h + dl;
                float4 cv = *(const float4*)(Cb2 + (size_t)d * LC + c4);
                float4 av = *(const float4*)(SP + dl * 132 + c4);
                float4 pr = make_float4(cv.x * av.x, cv.y * av.y, cv.z * av.z, cv.w * av.w);
                if (sel == 0) {
                    *(float4*)(outB + (size_t)d * LC + c4) = cv;
                    *(float4*)(outB + (size_t)(DD + d) * LC + c4) = av;
                    *(float4*)(outB + (size_t)(2 * DD + d) * LC + c4) = pr;
                } else {
                    *(float4*)(outB + (size_t)(3 * DD + d) * LC + c4) = pr;
                }
            }
        }
    }
}

extern "C" void kernel_launch(void* const* d_in, const int* in_sizes, int n_in,
                              void* d_out, int out_size) {
    const float* C = (const float*)d_in[0];
    const float* Q = (const float*)d_in[1];
    const int* Cmask = (const int*)d_in[2];
    const int* Qmask = (const int*)d_in[3];
    const float* w4C = (const float*)d_in[4];
    const float* w4Q = (const float*)d_in[5];
    const float* w4mlu = (const float*)d_in[6];
    const float* bias = (const float*)d_in[7];
    float* out = (float*)d_out;

    cudaFuncSetAttribute(k_scores, cudaFuncAttributeMaxDynamicSharedMemorySize, SMEM_BYTES);
    cudaFuncSetAttribute(k_gemmV2, cudaFuncAttributeMaxDynamicSharedMemorySize, SMEM_BYTES);
    cudaFuncSetAttribute(k_gemmAB, cudaFuncAttributeMaxDynamicSharedMemorySize, SMEM_BYTES);

    int nsub = BB * LC + BB * LQ;
    k_sub<<<(nsub + 255) / 256, 256>>>(C, Q, w4C, w4Q, bias);
    k_scores<<<dim3(4, 16, 16), 256, SMEM_BYTES>>>(C, Q, w4mlu, Qmask, Cmask);
    k_rmerge<<<(BB * LC + 255) / 256, 256>>>();
    k_cmerge<<<(BB * LQ + 255) / 256, 256>>>();
    k_gemmV2<<<dim3(4, 4, 16), 256, SMEM_BYTES>>>(C, Cmask);
    k_reduceV2<<<(BB * LQ * DD / 4 + 255) / 256, 256>>>();
    k_gemmAB<<<dim3(16, 16), 256, SMEM_BYTES>>>(Q, Qmask, C, out);
}